// round 17
// baseline (speedup 1.0000x reference)
#include <cuda_runtime.h>
#include <cuda_bf16.h>
#include <math.h>
#include <stdint.h>

#define GMM_D 64
#define GMM_K 64
#define TPB   128

typedef unsigned long long ull;

// W in constant memory: k-major pairs. cWB[k*32+jp] = (B[k][2jp], B[k][2jp+1])
__constant__ ull   cWB[GMM_K * 32];       // B  = mu * e^{-lv}
__constant__ ull   cWA[GMM_K * 32];       // A' = -0.5 * e^{-lv}
__constant__ float cC[GMM_K];             // -0.5*sum_d(lv + mu^2 e^{-lv}) + lp[k]

__device__ ull   g_wB[GMM_K * 32];
__device__ ull   g_wA[GMM_K * 32];
__device__ float g_C[GMM_K];
__device__ int   g_flag;

__device__ __forceinline__ ull fma2(ull a, ull b, ull c) {
    ull d; asm("fma.rn.f32x2 %0, %1, %2, %3;" : "=l"(d) : "l"(a), "l"(b), "l"(c)); return d;
}
__device__ __forceinline__ ull mul2(ull a, ull b) {
    ull d; asm("mul.rn.f32x2 %0, %1, %2;" : "=l"(d) : "l"(a), "l"(b)); return d;
}
__device__ __forceinline__ ull add2(ull a, ull b) {
    ull d; asm("add.rn.f32x2 %0, %1, %2;" : "=l"(d) : "l"(a), "l"(b)); return d;
}
__device__ __forceinline__ ull pack2(float lo, float hi) {
    ull r; asm("mov.b64 %0, {%1, %2};" : "=l"(r) : "f"(lo), "f"(hi)); return r;
}
__device__ __forceinline__ void unpack2(ull v, float& lo, float& hi) {
    asm("mov.b64 {%0, %1}, %2;" : "=f"(lo), "=f"(hi) : "l"(v));
}

// ---------------------------------------------------------------------------
// Precompute W tiles (k-major pair layout), C[k], and logvar k-uniformity flag.
// ---------------------------------------------------------------------------
__global__ void gmm_pre(const float* __restrict__ mu,
                        const float* __restrict__ lv,
                        const float* __restrict__ lp) {
    __shared__ int sbad;
    const int t = threadIdx.x;
    if (t == 0) sbad = 0;
    __syncthreads();

    int bad = 0;
    #pragma unroll
    for (int i = 0; i < 8; i++) {
        int idx = i * 256 + t;            // 0..2047
        int k   = idx >> 5;
        int jp  = idx & 31;
        int d   = 2 * jp;
        float l0 = lv[k * GMM_D + d],  l1 = lv[k * GMM_D + d + 1];
        float m0 = mu[k * GMM_D + d],  m1 = mu[k * GMM_D + d + 1];
        bad |= (__float_as_int(l0) != __float_as_int(lv[d])) |
               (__float_as_int(l1) != __float_as_int(lv[d + 1]));
        float e0 = __expf(-l0), e1 = __expf(-l1);
        g_wB[idx] = pack2(m0 * e0, m1 * e1);
        g_wA[idx] = pack2(-0.5f * e0, -0.5f * e1);
    }
    if (bad) atomicOr(&sbad, 1);
    __syncthreads();
    if (t == 0) g_flag = sbad;

    if (t < GMM_K) {
        float s = 0.f;
        #pragma unroll 8
        for (int d = 0; d < GMM_D; d++) {
            float l = lv[t * GMM_D + d];
            float m = mu[t * GMM_D + d];
            s += l + m * m * __expf(-l);
        }
        g_C[t] = -0.5f * s + lp[t];
    }
}

// ---------------------------------------------------------------------------
// Main kernel: persistent, smem-free, one sample per lane.
// weighted[n,k] = sum_d x*B[k] (+ x^2*A'[k] if logvars not k-uniform) + C[k];
// k-uniform terms cancel in the log-softmax over k.
// W access is warp-uniform (index independent of tid) -> ULDC uniform path;
// x row lives in registers; w[64] lives in registers; epilogue thread-local.
// ---------------------------------------------------------------------------
__global__ void __launch_bounds__(TPB, 2)
gmm_main(const float* __restrict__ X, float* __restrict__ out,
         int N, int nchunks, int nwarps) {
    const int lane = threadIdx.x & 31;
    const int gw   = (blockIdx.x * TPB + threadIdx.x) >> 5;
    const int general = g_flag;

    for (int chunk = gw; chunk < nchunks; chunk += nwarps) {
        const int n = chunk * 32 + lane;

        // ---- load this lane's sample row into registers (16 LDG.128) ----
        ull x[32];
        {
            const ulonglong2* xr = (const ulonglong2*)(X + (size_t)n * GMM_D);
            #pragma unroll
            for (int i = 0; i < 16; i++) {
                ulonglong2 v = xr[i];
                x[2 * i] = v.x; x[2 * i + 1] = v.y;
            }
        }

        // ---- per-k dot products; W via uniform constant loads ----
        float w[GMM_K];
        if (!general) {
            #pragma unroll
            for (int k = 0; k < GMM_K; k++) {
                ull a0 = 0ull, a1 = 0ull, a2 = 0ull, a3 = 0ull;
                #pragma unroll
                for (int j = 0; j < 32; j += 4) {
                    a0 = fma2(x[j],     cWB[k * 32 + j],     a0);
                    a1 = fma2(x[j + 1], cWB[k * 32 + j + 1], a1);
                    a2 = fma2(x[j + 2], cWB[k * 32 + j + 2], a2);
                    a3 = fma2(x[j + 3], cWB[k * 32 + j + 3], a3);
                }
                a0 = add2(a0, a1); a2 = add2(a2, a3); a0 = add2(a0, a2);
                float lo, hi; unpack2(a0, lo, hi);
                w[k] = lo + hi + cC[k];
            }
        } else {
            #pragma unroll
            for (int k = 0; k < GMM_K; k++) {
                ull a0 = 0ull, a1 = 0ull, a2 = 0ull, a3 = 0ull;
                #pragma unroll
                for (int j = 0; j < 32; j += 4) {
                    a0 = fma2(x[j],     cWB[k * 32 + j],     a0);
                    a1 = fma2(x[j + 1], cWB[k * 32 + j + 1], a1);
                    a2 = fma2(x[j + 2], cWB[k * 32 + j + 2], a2);
                    a3 = fma2(x[j + 3], cWB[k * 32 + j + 3], a3);
                    a0 = fma2(mul2(x[j],     x[j]),     cWA[k * 32 + j],     a0);
                    a1 = fma2(mul2(x[j + 1], x[j + 1]), cWA[k * 32 + j + 1], a1);
                    a2 = fma2(mul2(x[j + 2], x[j + 2]), cWA[k * 32 + j + 2], a2);
                    a3 = fma2(mul2(x[j + 3], x[j + 3]), cWA[k * 32 + j + 3], a3);
                }
                a0 = add2(a0, a1); a2 = add2(a2, a3); a0 = add2(a0, a2);
                float lo, hi; unpack2(a0, lo, hi);
                w[k] = lo + hi + cC[k];
            }
        }

        // ---- thread-local logsumexp over k ----
        float mx = w[0];
        #pragma unroll
        for (int k = 1; k < GMM_K; k++) mx = fmaxf(mx, w[k]);
        float s = 0.f;
        #pragma unroll
        for (int k = 0; k < GMM_K; k++) s += __expf(w[k] - mx);
        const float lse = mx + __logf(s);

        // ---- lane-coalesced stores (128B per warp-instr) ----
        #pragma unroll
        for (int k = 0; k < GMM_K; k++)
            out[(size_t)k * N + n] = w[k] - lse;
    }
}

extern "C" void kernel_launch(void* const* d_in, const int* in_sizes, int n_in,
                              void* d_out, int out_size) {
    const float* X  = (const float*)d_in[0];
    const float* mu = (const float*)d_in[1];
    const float* lv = (const float*)d_in[2];
    const float* lp = (const float*)d_in[3];
    float* out = (float*)d_out;

    const int K = in_sizes[3];            // 64
    const int D = in_sizes[1] / K;        // 64
    const int N = in_sizes[0] / D;        // 131072

    gmm_pre<<<1, 256>>>(mu, lv, lp);

    // copy precomputed W/C into constant memory (DtoD memcpy nodes; graph-legal)
    void *pB = nullptr, *pA = nullptr, *pC = nullptr;
    cudaGetSymbolAddress(&pB, g_wB);
    cudaGetSymbolAddress(&pA, g_wA);
    cudaGetSymbolAddress(&pC, g_C);
    cudaMemcpyToSymbolAsync(cWB, pB, sizeof(ull) * GMM_K * 32, 0,
                            cudaMemcpyDeviceToDevice, 0);
    cudaMemcpyToSymbolAsync(cWA, pA, sizeof(ull) * GMM_K * 32, 0,
                            cudaMemcpyDeviceToDevice, 0);
    cudaMemcpyToSymbolAsync(cC, pC, sizeof(float) * GMM_K, 0,
                            cudaMemcpyDeviceToDevice, 0);

    const int nchunks = N / 32;           // 4096
    const int grid    = 296;              // 2 per SM x 148 SMs
    const int nwarps  = grid * (TPB / 32);
    gmm_main<<<grid, TPB>>>(X, out, N, nchunks, nwarps);
}